// round 4
// baseline (speedup 1.0000x reference)
#include <cuda_runtime.h>
#include <cuda_fp16.h>
#include <cstdint>

// Problem constants (fixed shapes per reference)
#define DIMC 128
#define KC   65536
#define BC   1024
#define LC   512
#define PC   8388608

#define P4   (PC / 4)          // float4 count = 2097152
#define P4H  (P4 / 2)          // half of it   = 1048576

// Scratch (device global — no allocation allowed)
__device__ __half g_qTh[(size_t)KC * DIMC];     // 16 MB transposed queue [K, DIM] fp16

// ---------------------------------------------------------------------------
// EMA helper: one block = 256 float4s
// ---------------------------------------------------------------------------
__device__ __forceinline__ void ema_block(const float* __restrict__ pq,
                                          const float* __restrict__ pk,
                                          float* __restrict__ new_pk,
                                          int i) {
    float4 a  = __ldcs(reinterpret_cast<const float4*>(pq) + i);
    float4 b4 = __ldcs(reinterpret_cast<const float4*>(pk) + i);
    float4 r = make_float4(b4.x * 0.7f + a.x * 0.3f,
                           b4.y * 0.7f + a.y * 0.3f,
                           b4.z * 0.7f + a.z * 0.3f,
                           b4.w * 0.7f + a.w * 0.3f);
    __stcs(reinterpret_cast<float4*>(new_pk) + i, r);
}

// ---------------------------------------------------------------------------
// Kernel A: 12288 blocks, pattern [tile, tile, EMA] repeating.
//   tile blocks (8192): 32x32 tile of queue [DIM, K]
//     - fp16 transposed original values -> g_qTh (L2-resident for gather)
//     - new_queue = queue with cols [ptr,ptr+B) replaced by normalize(keys).T
//   EMA blocks (4096): first half of param EMA stream
// ---------------------------------------------------------------------------
__global__ void tile_ema_kernel(const float* __restrict__ queue,
                                const float* __restrict__ keys,
                                float* __restrict__ new_queue,
                                const int* __restrict__ ptrp,
                                const float* __restrict__ pq,
                                const float* __restrict__ pk,
                                float* __restrict__ new_pk) {
    int grp = blockIdx.x / 3;
    int sub = blockIdx.x - grp * 3;

    if (sub == 2) {   // EMA role: first half
        ema_block(pq, pk, new_pk, grp * 256 + (int)threadIdx.x);
        return;
    }

    int tb = grp * 2 + sub;            // tile block id 0..8191
    __shared__ float tile[32][33];
    __shared__ float skey[32][33];

    int bx = tb & 2047;                // k-tile index (0..2047)
    int by = tb >> 11;                 // d-tile index (0..3)
    int k0 = bx << 5;
    int d0 = by << 5;
    int tx = threadIdx.x & 31;
    int wy = threadIdx.x >> 5;         // warp id 0..7
    int ptr = *ptrp;

    #pragma unroll
    for (int j = 0; j < 32; j += 8)
        tile[wy + j][tx] = __ldcs(&queue[(size_t)(d0 + wy + j) * KC + (k0 + tx)]);
    __syncthreads();

    // transposed fp16 write of ORIGINAL values
    #pragma unroll
    for (int j = 0; j < 32; j += 8)
        g_qTh[(size_t)(k0 + wy + j) * DIMC + (d0 + tx)] = __float2half(tile[tx][wy + j]);

    // on-the-fly normalization of key rows for replaced columns in this tile
    int lo = ptr - k0;          if (lo < 0)  lo = 0;
    int hi = ptr + BC - k0;     if (hi > 32) hi = 32;
    if (lo < hi) {
        #pragma unroll
        for (int cc = 0; cc < 4; ++cc) {
            int c = wy + (cc << 3);
            if (c >= lo && c < hi) {
                int r = k0 + c - ptr;
                float4 v = reinterpret_cast<const float4*>(keys + (size_t)r * DIMC)[tx];
                float s = v.x * v.x + v.y * v.y + v.z * v.z + v.w * v.w;
                #pragma unroll
                for (int o = 16; o > 0; o >>= 1) s += __shfl_xor_sync(0xFFFFFFFFu, s, o);
                float inv = 1.0f / sqrtf(s);
                int dd = (tx << 2) - d0;
                if (dd >= 0 && dd < 32) {
                    skey[c][dd + 0] = v.x * inv;
                    skey[c][dd + 1] = v.y * inv;
                    skey[c][dd + 2] = v.z * inv;
                    skey[c][dd + 3] = v.w * inv;
                }
            }
        }
        __syncthreads();
    }

    unsigned rcol = (unsigned)(k0 + tx - ptr);
    #pragma unroll
    for (int j = 0; j < 32; j += 8) {
        float val = tile[wy + j][tx];
        if (rcol < (unsigned)BC) val = skey[tx][wy + j];
        __stcs(&new_queue[(size_t)(d0 + wy + j) * KC + (k0 + tx)], val);
    }
}

// ---------------------------------------------------------------------------
// Kernel B: 5120 blocks, pattern [logits, EMA, EMA, EMA, EMA] repeating.
//   logits blocks (1024): fp16 gather dot for one batch row b
//   EMA blocks (4096): second half of param EMA stream
// ---------------------------------------------------------------------------
__global__ void logits_ema_kernel(const float* __restrict__ q,
                                  const int* __restrict__ sidx,
                                  const float* __restrict__ pq,
                                  const float* __restrict__ pk,
                                  float* __restrict__ logits,
                                  float* __restrict__ labels,
                                  float* __restrict__ new_pk) {
    int grp = blockIdx.x / 5;
    int sub = blockIdx.x - grp * 5;

    if (sub != 0) {   // EMA role: second half
        int ema_id = grp * 4 + (sub - 1);
        ema_block(pq, pk, new_pk, P4H + ema_id * 256 + (int)threadIdx.x);
        return;
    }

    int b = grp;      // 0..1023
    __shared__ float4 qs4[32];
    int tid = threadIdx.x;
    if (tid < 32) {
        float4 v = reinterpret_cast<const float4*>(q + (size_t)b * DIMC)[tid];
        float s = v.x * v.x + v.y * v.y + v.z * v.z + v.w * v.w;
        #pragma unroll
        for (int o = 16; o > 0; o >>= 1) s += __shfl_xor_sync(0xFFFFFFFFu, s, o);
        float inv = 1.0f / sqrtf(s);
        qs4[tid] = make_float4(v.x * inv, v.y * inv, v.z * inv, v.w * inv);
    }
    if (tid == 0) labels[b] = 0.0f;
    __syncthreads();

    int lane    = tid & 31;
    int warp    = tid >> 5;      // 0..7
    int half_id = lane >> 4;     // which of the 2 samples this lane serves
    int subl    = lane & 15;     // position within the 16-lane group

    float4 qa = qs4[subl * 2];
    float4 qb = qs4[subl * 2 + 1];

    const int* row = sidx + (size_t)b * LC;
    float* lrow = logits + (size_t)b * LC;

    #pragma unroll 4
    for (int l = warp * 2; l < LC; l += 16) {
        int idx = row[l + half_id];
        int4 pkt = reinterpret_cast<const int4*>(g_qTh + (size_t)idx * DIMC)[subl];
        float2 f0 = __half22float2(*reinterpret_cast<__half2*>(&pkt.x));
        float2 f1 = __half22float2(*reinterpret_cast<__half2*>(&pkt.y));
        float2 f2 = __half22float2(*reinterpret_cast<__half2*>(&pkt.z));
        float2 f3 = __half22float2(*reinterpret_cast<__half2*>(&pkt.w));
        float s = f0.x * qa.x + f0.y * qa.y + f1.x * qa.z + f1.y * qa.w
                + f2.x * qb.x + f2.y * qb.y + f3.x * qb.z + f3.y * qb.w;
        #pragma unroll
        for (int o = 8; o > 0; o >>= 1)
            s += __shfl_xor_sync(0xFFFFFFFFu, s, o);
        if (subl == 0)
            lrow[l + half_id] = s * (1.0f / 0.09f);
    }
}

// ---------------------------------------------------------------------------
extern "C" void kernel_launch(void* const* d_in, const int* in_sizes, int n_in,
                              void* d_out, int out_size) {
    const float* q        = (const float*)d_in[0];
    const float* queue    = (const float*)d_in[1];
    const float* keys     = (const float*)d_in[2];
    const float* param_q  = (const float*)d_in[3];
    const float* param_k  = (const float*)d_in[4];
    const int*   sidx     = (const int*)  d_in[5];
    const int*   ptr      = (const int*)  d_in[6];

    float* out       = (float*)d_out;
    float* logits    = out;                            // B*L = 524288
    float* labels    = logits + (size_t)BC * LC;       // 1024
    float* new_queue = labels + BC;                    // DIM*K = 8388608
    float* new_pk    = new_queue + (size_t)DIMC * KC;  // P = 8388608

    // Kernel A: tiles (transpose + enqueue/copy) interleaved with half the EMA
    tile_ema_kernel<<<12288, 256>>>(queue, keys, new_queue, ptr,
                                    param_q, param_k, new_pk);

    // Kernel B: logits gather interleaved with the other half of the EMA
    logits_ema_kernel<<<5120, 256>>>(q, sidx, param_q, param_k,
                                     logits, labels, new_pk);
}

// round 5
// speedup vs baseline: 1.0098x; 1.0098x over previous
#include <cuda_runtime.h>
#include <cuda_fp16.h>
#include <cstdint>

// Problem constants (fixed shapes per reference)
#define DIMC 128
#define KC   65536
#define BC   1024
#define LC   512
#define PC   8388608

// Scratch (device global — no allocation allowed)
__device__ __half g_qTh[(size_t)KC * DIMC];     // 16 MB transposed queue [K, DIM] fp16

// ---------------------------------------------------------------------------
// Kernel A: 2048 blocks; block = 32 k-columns x full 128 dims of queue [DIM,K]
//   - fp16 transposed original values -> g_qTh (256B contiguous stores)
//   - new_queue = queue with cols [ptr,ptr+B) replaced by normalize(keys).T
// smem tile[k][d] with row stride 129: conflict-free in every phase.
// ---------------------------------------------------------------------------
__global__ __launch_bounds__(256) void tile_kernel(
        const float* __restrict__ queue,
        const float* __restrict__ keys,
        float* __restrict__ new_queue,
        const int* __restrict__ ptrp) {
    __shared__ float tile[32][129];

    int k0   = blockIdx.x << 5;
    int lane = threadIdx.x & 31;
    int wy   = threadIdx.x >> 5;       // warp id 0..7
    int ptr  = *ptrp;

    // Phase 1: load 128 rows x 32 cols; lane covers k0+lane (128B per row)
    #pragma unroll
    for (int i = 0; i < 16; ++i) {
        int d = wy * 16 + i;
        tile[lane][d] = __ldcs(&queue[(size_t)d * KC + (k0 + lane)]);
    }
    __syncthreads();

    // Phase 2: fp16 transposed store of ORIGINAL values.
    // warp wy owns k = 4*wy..4*wy+3 ; lane covers d = 4*lane..4*lane+3 (8B)
    #pragma unroll
    for (int j = 0; j < 4; ++j) {
        int k = wy * 4 + j;
        float v0 = tile[k][4 * lane + 0];
        float v1 = tile[k][4 * lane + 1];
        float v2 = tile[k][4 * lane + 2];
        float v3 = tile[k][4 * lane + 3];
        __half2 h0 = __floats2half2_rn(v0, v1);
        __half2 h1 = __floats2half2_rn(v2, v3);
        uint2 pkt = make_uint2(*reinterpret_cast<unsigned*>(&h0),
                               *reinterpret_cast<unsigned*>(&h1));
        *reinterpret_cast<uint2*>(&g_qTh[(size_t)(k0 + k) * DIMC + 4 * lane]) = pkt;
    }

    // Phase 3: overwrite replaced columns with normalized keys (same warp's k)
    int lo = ptr - k0;          if (lo < 0)  lo = 0;
    int hi = ptr + BC - k0;     if (hi > 32) hi = 32;
    if (lo < hi) {
        #pragma unroll
        for (int j = 0; j < 4; ++j) {
            int k = wy * 4 + j;
            if (k >= lo && k < hi) {
                int r = k0 + k - ptr;               // key row
                float4 v = reinterpret_cast<const float4*>(keys + (size_t)r * DIMC)[lane];
                float s = v.x * v.x + v.y * v.y + v.z * v.z + v.w * v.w;
                #pragma unroll
                for (int o = 16; o > 0; o >>= 1) s += __shfl_xor_sync(0xFFFFFFFFu, s, o);
                float inv = 1.0f / sqrtf(s);
                tile[k][4 * lane + 0] = v.x * inv;
                tile[k][4 * lane + 1] = v.y * inv;
                tile[k][4 * lane + 2] = v.z * inv;
                tile[k][4 * lane + 3] = v.w * inv;
            }
        }
    }
    __syncthreads();

    // Phase 4: write new_queue rows (streamed)
    #pragma unroll
    for (int i = 0; i < 16; ++i) {
        int d = wy * 16 + i;
        __stcs(&new_queue[(size_t)d * KC + (k0 + lane)], tile[lane][d]);
    }
}

// ---------------------------------------------------------------------------
// Kernel B: grid = 2048 logits blocks + 2048 EMA blocks (in that launch order).
//   logits block: half a batch row (256 samples), fp16 L2-resident gather.
//   EMA block: 1024 float4s, 4 per thread, 8 independent loads in flight.
// ---------------------------------------------------------------------------
__global__ __launch_bounds__(256) void logits_ema_kernel(
        const float* __restrict__ q,
        const int* __restrict__ sidx,
        const float* __restrict__ pq,
        const float* __restrict__ pk,
        float* __restrict__ logits,
        float* __restrict__ labels,
        float* __restrict__ new_pk) {
    if (blockIdx.x < 2048) {
        int b   = blockIdx.x >> 1;
        int seg = blockIdx.x & 1;          // which 256-sample half
        __shared__ float4 qs4[32];
        int tid = threadIdx.x;
        if (tid < 32) {
            float4 v = reinterpret_cast<const float4*>(q + (size_t)b * DIMC)[tid];
            float s = v.x * v.x + v.y * v.y + v.z * v.z + v.w * v.w;
            #pragma unroll
            for (int o = 16; o > 0; o >>= 1) s += __shfl_xor_sync(0xFFFFFFFFu, s, o);
            float inv = 1.0f / sqrtf(s);
            qs4[tid] = make_float4(v.x * inv, v.y * inv, v.z * inv, v.w * inv);
        }
        if (tid == 0 && seg == 0) labels[b] = 0.0f;
        __syncthreads();

        int lane    = tid & 31;
        int warp    = tid >> 5;      // 0..7
        int half_id = lane >> 4;     // which of the 2 samples this lane serves
        int subl    = lane & 15;     // position within the 16-lane group

        float4 qa = qs4[subl * 2];
        float4 qb = qs4[subl * 2 + 1];

        const int* row = sidx + (size_t)b * LC + seg * 256;
        float* lrow = logits + (size_t)b * LC + seg * 256;

        #pragma unroll 4
        for (int l = warp * 2; l < 256; l += 16) {
            int idx = row[l + half_id];
            int4 pkt = reinterpret_cast<const int4*>(g_qTh + (size_t)idx * DIMC)[subl];
            float2 f0 = __half22float2(*reinterpret_cast<__half2*>(&pkt.x));
            float2 f1 = __half22float2(*reinterpret_cast<__half2*>(&pkt.y));
            float2 f2 = __half22float2(*reinterpret_cast<__half2*>(&pkt.z));
            float2 f3 = __half22float2(*reinterpret_cast<__half2*>(&pkt.w));
            float s = f0.x * qa.x + f0.y * qa.y + f1.x * qa.z + f1.y * qa.w
                    + f2.x * qb.x + f2.y * qb.y + f3.x * qb.z + f3.y * qb.w;
            #pragma unroll
            for (int o = 8; o > 0; o >>= 1)
                s += __shfl_xor_sync(0xFFFFFFFFu, s, o);
            if (subl == 0)
                lrow[l + half_id] = s * (1.0f / 0.09f);
        }
    } else {
        // EMA: new_pk = 0.7*pk + 0.3*pq ; 1024 float4s per block, MLP=8
        int base = (blockIdx.x - 2048) * 1024 + (int)threadIdx.x;
        const float4* pq4 = reinterpret_cast<const float4*>(pq);
        const float4* pk4 = reinterpret_cast<const float4*>(pk);
        float4* out4 = reinterpret_cast<float4*>(new_pk);
        float4 a0 = __ldcs(pq4 + base);
        float4 b0 = __ldcs(pk4 + base);
        float4 a1 = __ldcs(pq4 + base + 256);
        float4 b1 = __ldcs(pk4 + base + 256);
        float4 a2 = __ldcs(pq4 + base + 512);
        float4 b2 = __ldcs(pk4 + base + 512);
        float4 a3 = __ldcs(pq4 + base + 768);
        float4 b3 = __ldcs(pk4 + base + 768);
        float4 r0 = make_float4(b0.x*0.7f+a0.x*0.3f, b0.y*0.7f+a0.y*0.3f,
                                b0.z*0.7f+a0.z*0.3f, b0.w*0.7f+a0.w*0.3f);
        float4 r1 = make_float4(b1.x*0.7f+a1.x*0.3f, b1.y*0.7f+a1.y*0.3f,
                                b1.z*0.7f+a1.z*0.3f, b1.w*0.7f+a1.w*0.3f);
        float4 r2 = make_float4(b2.x*0.7f+a2.x*0.3f, b2.y*0.7f+a2.y*0.3f,
                                b2.z*0.7f+a2.z*0.3f, b2.w*0.7f+a2.w*0.3f);
        float4 r3 = make_float4(b3.x*0.7f+a3.x*0.3f, b3.y*0.7f+a3.y*0.3f,
                                b3.z*0.7f+a3.z*0.3f, b3.w*0.7f+a3.w*0.3f);
        __stcs(out4 + base,       r0);
        __stcs(out4 + base + 256, r1);
        __stcs(out4 + base + 512, r2);
        __stcs(out4 + base + 768, r3);
    }
}

// ---------------------------------------------------------------------------
extern "C" void kernel_launch(void* const* d_in, const int* in_sizes, int n_in,
                              void* d_out, int out_size) {
    const float* q        = (const float*)d_in[0];
    const float* queue    = (const float*)d_in[1];
    const float* keys     = (const float*)d_in[2];
    const float* param_q  = (const float*)d_in[3];
    const float* param_k  = (const float*)d_in[4];
    const int*   sidx     = (const int*)  d_in[5];
    const int*   ptr      = (const int*)  d_in[6];

    float* out       = (float*)d_out;
    float* logits    = out;                            // B*L = 524288
    float* labels    = logits + (size_t)BC * LC;       // 1024
    float* new_queue = labels + BC;                    // DIM*K = 8388608
    float* new_pk    = new_queue + (size_t)DIMC * KC;  // P = 8388608

    // Kernel A: fp16 transpose + fp32 enqueue/copy (one read of queue)
    tile_kernel<<<2048, 256>>>(queue, keys, new_queue, ptr);

    // Kernel B: logits gather (2048 blocks) then EMA (2048 blocks)
    logits_ema_kernel<<<4096, 256>>>(q, sidx, param_q, param_k,
                                     logits, labels, new_pk);
}